// round 1
// baseline (speedup 1.0000x reference)
#include <cuda_runtime.h>

// ---------------------------------------------------------------------------
// Problem constants
// ---------------------------------------------------------------------------
#define NB      4
#define CDIM    64
#define HDIM    256
#define WDIM    256
#define HW      65536          // 256*256
#define WS      16
#define NWIN    1024           // 4 * 16 * 16
#define LSEQ    256            // 16*16
#define DIN     128            // d_inner
#define DSTATE  16
#define DTRANK  4
#define NDBL    36             // dt_rank + 2*d_state
#define M_TOT   (NWIN * LSEQ)  // 262144 token positions

// ---------------------------------------------------------------------------
// Scratch (static device globals — allocation-free per harness rules)
// ---------------------------------------------------------------------------
__device__ float g_xw [M_TOT * CDIM];   // LN1 output, windowed (win*256+l, 64)
__device__ float g_xz [M_TOT * 256];    // in_proj out: cols 0..127 xm, 128..255 z
__device__ float g_xc [M_TOT * DIN];    // conv+silu output
__device__ float g_dbl[M_TOT * NDBL];   // x_proj out (dt_in | B | C)
__device__ float g_dt [M_TOT * DIN];    // softplus(dt_proj(..))
__device__ float g_y  [M_TOT * DIN];    // scan+gate output
__device__ float g_x2 [NB * CDIM * HW]; // x + attn (NCHW)
__device__ float g_y2 [M_TOT * CDIM];   // LN3 output, pos-major (pos, 64)
__device__ float g_hid[M_TOT * 256];    // ffn_in output (pos, 256)
__device__ float g_g  [M_TOT * DIN];    // gelu(h1)*h2
__device__ float g_Atab[DIN * DSTATE];  // A = -exp(A_log)
__device__ int   g_flag;                // 1 if A[d][s] == -(s+1)

// ---------------------------------------------------------------------------
// prep: A table + structure flag
// ---------------------------------------------------------------------------
__global__ void prep_kernel(const float* __restrict__ alog,
                            float* __restrict__ Atab, int* __restrict__ flag)
{
    __shared__ int ok_s;
    if (threadIdx.x == 0) ok_s = 1;
    __syncthreads();
    bool ok = true;
    for (int i = threadIdx.x; i < DIN * DSTATE; i += 256) {
        float a = -expf(alog[i]);
        Atab[i] = a;
        int s = i & 15;
        if (fabsf(a + (float)(s + 1)) > 1e-3f * (float)(s + 1)) ok = false;
    }
    if (!ok) atomicAnd(&ok_s, 0);
    __syncthreads();
    if (threadIdx.x == 0) *flag = ok_s;
}

// ---------------------------------------------------------------------------
// Channel LayerNorm (over 64 channels per spatial pos).
// mode 0: write windowed layout (win*256+l, c)   [LN2 -> mamba input]
// mode 1: write pos-major raster (b*65536+hw, c) [LN3 -> ffn input]
// One block = 64 consecutive w positions in one row h of one image.
// ---------------------------------------------------------------------------
__global__ void __launch_bounds__(256) ln_kernel(
    const float* __restrict__ x, const float* __restrict__ gam,
    const float* __restrict__ bet, float* __restrict__ out, int mode)
{
    __shared__ float s[64][65];
    __shared__ float mu[64], rs[64];
    int tid  = threadIdx.x;
    int blk  = blockIdx.x;
    int bimg = blk >> 10;
    int rem  = blk & 1023;
    int h    = rem >> 2;
    int w0   = (rem & 3) << 6;
    const float* xb = x + ((bimg * CDIM) << 16) + (h << 8) + w0;

#pragma unroll
    for (int i = 0; i < 16; i++) {
        int idx = i * 256 + tid;
        int c = idx >> 6, p = idx & 63;
        s[p][c] = xb[(c << 16) + p];
    }
    __syncthreads();
    if (tid < 64) {
        float sum = 0.f, sq = 0.f;
#pragma unroll
        for (int c = 0; c < 64; c++) { float v = s[tid][c]; sum += v; sq += v * v; }
        float m = sum * (1.f / 64.f);
        float var = sq * (1.f / 64.f) - m * m;
        mu[tid] = m;
        rs[tid] = rsqrtf(var + 1e-5f);
    }
    __syncthreads();
#pragma unroll
    for (int i = 0; i < 16; i++) {
        int c = tid & 63;
        int p = (i << 2) + (tid >> 6);
        float v = (s[p][c] - mu[p]) * rs[p] * gam[c] + bet[c];
        int wg = w0 + p;
        int addr;
        if (mode == 0) {
            int win = (bimg << 8) + ((h >> 4) << 4) + (wg >> 4);
            int l   = ((h & 15) << 4) + (wg & 15);
            addr = ((win << 8) + l) * CDIM + c;
        } else {
            addr = (((bimg << 16) + (h << 8) + wg) << 6) + c;
        }
        out[addr] = v;
    }
}

// ---------------------------------------------------------------------------
// Generic fp32 SIMT GEMM: C[M,N] = A[M,K] @ W[N,K]^T
// BM=128, BN=64, BK=16, 256 threads, 8x4 per-thread microtile.
// EP 0: C[m*ldc+n]
// EP 1: out_proj epilogue: m=win*256+l -> NCHW, C = res + acc
// EP 2: ffn_out epilogue:  m=b*65536+hw -> NCHW, C = res + acc
// ---------------------------------------------------------------------------
template<int EP>
__global__ void __launch_bounds__(256) gemm_kernel(
    const float* __restrict__ A, const float* __restrict__ W,
    float* __restrict__ C, const float* __restrict__ res,
    int M, int N, int K, int ldc)
{
    __shared__ float As[16][128];
    __shared__ float Bs[16][64];
    int tid = threadIdx.x;
    int m0 = blockIdx.x * 128;
    int n0 = blockIdx.y * 64;
    int tym = tid >> 4;       // 0..15
    int txn = tid & 15;       // 0..15
    int ar = tid >> 2;        // 0..63
    int ak = (tid & 3) << 2;  // 0,4,8,12

    float acc[8][4];
#pragma unroll
    for (int i = 0; i < 8; i++)
#pragma unroll
        for (int j = 0; j < 4; j++) acc[i][j] = 0.f;

    for (int k0 = 0; k0 < K; k0 += 16) {
#pragma unroll
        for (int pp = 0; pp < 2; pp++) {
            int r = ar + pp * 64;
            float4 v = *(const float4*)&A[(m0 + r) * K + k0 + ak];
            As[ak + 0][r] = v.x; As[ak + 1][r] = v.y;
            As[ak + 2][r] = v.z; As[ak + 3][r] = v.w;
        }
        {
            int n = ar;
            float4 v = make_float4(0.f, 0.f, 0.f, 0.f);
            if (n0 + n < N) v = *(const float4*)&W[(n0 + n) * K + k0 + ak];
            Bs[ak + 0][n] = v.x; Bs[ak + 1][n] = v.y;
            Bs[ak + 2][n] = v.z; Bs[ak + 3][n] = v.w;
        }
        __syncthreads();
#pragma unroll
        for (int kk = 0; kk < 16; kk++) {
            float a[8], b[4];
            *(float4*)&a[0] = *(const float4*)&As[kk][tym * 8];
            *(float4*)&a[4] = *(const float4*)&As[kk][tym * 8 + 4];
            *(float4*)&b[0] = *(const float4*)&Bs[kk][txn * 4];
#pragma unroll
            for (int i = 0; i < 8; i++)
#pragma unroll
                for (int j = 0; j < 4; j++) acc[i][j] = fmaf(a[i], b[j], acc[i][j]);
        }
        __syncthreads();
    }

#pragma unroll
    for (int i = 0; i < 8; i++) {
        int m = m0 + tym * 8 + i;
#pragma unroll
        for (int j = 0; j < 4; j++) {
            int n = n0 + txn * 4 + j;
            if (n < N) {
                float v = acc[i][j];
                if (EP == 0) {
                    C[m * ldc + n] = v;
                } else if (EP == 1) {
                    int win = m >> 8, l = m & 255;
                    int b = win >> 8, widx = win & 255;
                    int h = ((widx >> 4) << 4) + (l >> 4);
                    int w = ((widx & 15) << 4) + (l & 15);
                    int addr = ((b * CDIM + n) << 16) + (h << 8) + w;
                    C[addr] = res[addr] + v;
                } else {
                    int b = m >> 16, hw = m & 65535;
                    int addr = ((b * CDIM + n) << 16) + hw;
                    C[addr] = res[addr] + v;
                }
            }
        }
    }
}

// ---------------------------------------------------------------------------
// Depthwise causal conv1d (k=4, left pad 3) + bias + SiLU.
// ---------------------------------------------------------------------------
__global__ void __launch_bounds__(256) conv_kernel(
    const float* __restrict__ xz, const float* __restrict__ cw,
    const float* __restrict__ cb, float* __restrict__ xc)
{
    int gid = blockIdx.x * 256 + threadIdx.x;
    int d = gid & 127;
    int m = gid >> 7;
    int t = m & 255;
    float acc = cb[d];
#pragma unroll
    for (int j = 0; j < 4; j++) {
        int tt = t - 3 + j;
        if (tt >= 0) acc += cw[(d << 2) + j] * xz[((m - 3 + j) << 8) + d];
    }
    float e = __expf(-acc);
    xc[gid] = __fdividef(acc, 1.f + e);   // silu
}

// ---------------------------------------------------------------------------
// dt = softplus(dbl[:, :4] @ dt_proj_w^T + dt_proj_b)
// ---------------------------------------------------------------------------
__global__ void __launch_bounds__(256) dt_kernel(
    const float* __restrict__ dbl, const float* __restrict__ dtw,
    const float* __restrict__ dtb, float* __restrict__ dt)
{
    int gid = blockIdx.x * 256 + threadIdx.x;
    int d = gid & 127;
    int m = gid >> 7;
    float4 q = *(const float4*)(dbl + m * NDBL);       // cols 0..3 (16B aligned)
    float4 wv = *(const float4*)(dtw + (d << 2));
    float v = dtb[d] + q.x * wv.x + q.y * wv.y + q.z * wv.z + q.w * wv.w;
    dt[gid] = (v > 15.f) ? v : log1pf(__expf(v));
}

// ---------------------------------------------------------------------------
// Selective scan + skip(D) + SiLU(z) gate. One block per window, thread = d.
// Fast path exploits A[d][s] = -(s+1): decay_s = r^(s+1), r = exp(-dt).
// ---------------------------------------------------------------------------
__global__ void __launch_bounds__(128) scan_kernel(
    const float* __restrict__ dt, const float* __restrict__ dbl,
    const float* __restrict__ xc, const float* __restrict__ xz,
    const float* __restrict__ Dv, const float* __restrict__ Atab,
    const int* __restrict__ flagp, float* __restrict__ yout)
{
    int win = blockIdx.x;
    int d = threadIdx.x;
    int fl = *flagp;
    float Dd = Dv[d];
    float h[16];
#pragma unroll
    for (int s = 0; s < 16; s++) h[s] = 0.f;
    int mbase = win << 8;

    for (int t = 0; t < 256; t++) {
        int m = mbase + t;
        float dtv = dt[(m << 7) + d];
        float u   = xc[(m << 7) + d];
        float zv  = xz[(m << 8) + 128 + d];
        const float* row = dbl + m * NDBL;
        float4 B0 = *(const float4*)(row + 4);
        float4 B1 = *(const float4*)(row + 8);
        float4 B2 = *(const float4*)(row + 12);
        float4 B3 = *(const float4*)(row + 16);
        float4 C0 = *(const float4*)(row + 20);
        float4 C1 = *(const float4*)(row + 24);
        float4 C2 = *(const float4*)(row + 28);
        float4 C3 = *(const float4*)(row + 32);
        float Bv[16] = {B0.x,B0.y,B0.z,B0.w, B1.x,B1.y,B1.z,B1.w,
                        B2.x,B2.y,B2.z,B2.w, B3.x,B3.y,B3.z,B3.w};
        float Cv[16] = {C0.x,C0.y,C0.z,C0.w, C1.x,C1.y,C1.z,C1.w,
                        C2.x,C2.y,C2.z,C2.w, C3.x,C3.y,C3.z,C3.w};
        float dtu = dtv * u;
        float yv = 0.f;
        if (fl) {
            float r = __expf(-dtv);
            float p = r;
#pragma unroll
            for (int s = 0; s < 16; s++) {
                h[s] = h[s] * p + dtu * Bv[s];
                yv += h[s] * Cv[s];
                p *= r;
            }
        } else {
#pragma unroll
            for (int s = 0; s < 16; s++) {
                float dec = __expf(dtv * Atab[(d << 4) + s]);
                h[s] = h[s] * dec + dtu * Bv[s];
                yv += h[s] * Cv[s];
            }
        }
        yv += u * Dd;
        float sg = __fdividef(1.f, 1.f + __expf(-zv));
        yout[(m << 7) + d] = yv * zv * sg;   // y * silu(z)
    }
}

// ---------------------------------------------------------------------------
// Depthwise 3x3 SAME conv on hid (pos,256) + split + exact GELU gate.
// thread computes channels c and c+128, writes g = gelu(h1)*h2.
// ---------------------------------------------------------------------------
__global__ void __launch_bounds__(256) dw_kernel(
    const float* __restrict__ hid, const float* __restrict__ dww,
    float* __restrict__ gout)
{
    int gid = blockIdx.x * 256 + threadIdx.x;
    int c = gid & 127;
    int m = gid >> 7;
    int b = m >> 16, hw = m & 65535;
    int h = hw >> 8, w = hw & 255;
    float a1 = 0.f, a2 = 0.f;
#pragma unroll
    for (int dy = 0; dy < 3; dy++) {
        int hh = h + dy - 1;
        if (hh < 0 || hh > 255) continue;
#pragma unroll
        for (int dx = 0; dx < 3; dx++) {
            int ww = w + dx - 1;
            if (ww < 0 || ww > 255) continue;
            int mm = (b << 16) + (hh << 8) + ww;
            const float* row = hid + (mm << 8);
            a1 += dww[c * 9 + dy * 3 + dx] * row[c];
            a2 += dww[(c + 128) * 9 + dy * 3 + dx] * row[c + 128];
        }
    }
    float gl = 0.5f * a1 * (1.f + erff(a1 * 0.70710678118f));
    gout[gid] = gl * a2;
}

// ---------------------------------------------------------------------------
// launch
// ---------------------------------------------------------------------------
extern "C" void kernel_launch(void* const* d_in, const int* in_sizes, int n_in,
                              void* d_out, int out_size)
{
    (void)in_sizes; (void)n_in; (void)out_size;
    const float* x     = (const float*)d_in[0];
    const float* ln2w  = (const float*)d_in[1];
    const float* ln2b  = (const float*)d_in[2];
    const float* ln3w  = (const float*)d_in[3];
    const float* ln3b  = (const float*)d_in[4];
    const float* inpw  = (const float*)d_in[5];
    const float* convw = (const float*)d_in[6];
    const float* convb = (const float*)d_in[7];
    const float* xpw   = (const float*)d_in[8];
    const float* dtw   = (const float*)d_in[9];
    const float* dtb   = (const float*)d_in[10];
    const float* alog  = (const float*)d_in[11];
    const float* Dv    = (const float*)d_in[12];
    const float* outw  = (const float*)d_in[13];
    const float* fiw   = (const float*)d_in[14];
    const float* fdw   = (const float*)d_in[15];
    const float* fow   = (const float*)d_in[16];
    float* out = (float*)d_out;

    float *xw, *xz, *xc, *dbl, *dtp, *yb, *x2, *y2, *hid, *gg, *Atab;
    int* flag;
    cudaGetSymbolAddress((void**)&xw,  g_xw);
    cudaGetSymbolAddress((void**)&xz,  g_xz);
    cudaGetSymbolAddress((void**)&xc,  g_xc);
    cudaGetSymbolAddress((void**)&dbl, g_dbl);
    cudaGetSymbolAddress((void**)&dtp, g_dt);
    cudaGetSymbolAddress((void**)&yb,  g_y);
    cudaGetSymbolAddress((void**)&x2,  g_x2);
    cudaGetSymbolAddress((void**)&y2,  g_y2);
    cudaGetSymbolAddress((void**)&hid, g_hid);
    cudaGetSymbolAddress((void**)&gg,  g_g);
    cudaGetSymbolAddress((void**)&Atab, g_Atab);
    cudaGetSymbolAddress((void**)&flag, g_flag);

    prep_kernel<<<1, 256>>>(alog, Atab, flag);

    // LN2 + window partition
    ln_kernel<<<4096, 256>>>(x, ln2w, ln2b, xw, 0);

    // in_proj: (262144,64) @ (256,64)^T -> xz
    {
        dim3 g(M_TOT / 128, 4);
        gemm_kernel<0><<<g, 256>>>(xw, inpw, xz, nullptr, M_TOT, 256, 64, 256);
    }

    // depthwise causal conv1d + silu
    conv_kernel<<<(M_TOT * DIN) / 256, 256>>>(xz, convw, convb, xc);

    // x_proj: (262144,128) @ (36,128)^T -> dbl
    {
        dim3 g(M_TOT / 128, 1);
        gemm_kernel<0><<<g, 256>>>(xc, xpw, dbl, nullptr, M_TOT, NDBL, 128, NDBL);
    }

    // dt_proj + softplus
    dt_kernel<<<(M_TOT * DIN) / 256, 256>>>(dbl, dtw, dtb, dtp);

    // selective scan + D skip + silu(z) gate
    scan_kernel<<<NWIN, 128>>>(dtp, dbl, xc, xz, Dv, Atab, flag, yb);

    // out_proj + un-window + residual -> x2
    {
        dim3 g(M_TOT / 128, 1);
        gemm_kernel<1><<<g, 256>>>(yb, outw, x2, x, M_TOT, 64, 128, 0);
    }

    // LN3 -> y2 (pos-major)
    ln_kernel<<<4096, 256>>>(x2, ln3w, ln3b, y2, 1);

    // ffn_in: (262144,64) @ (256,64)^T -> hid
    {
        dim3 g(M_TOT / 128, 4);
        gemm_kernel<0><<<g, 256>>>(y2, fiw, hid, nullptr, M_TOT, 256, 64, 256);
    }

    // depthwise 3x3 + gelu gate -> gg
    dw_kernel<<<(M_TOT * DIN) / 256, 256>>>(hid, fdw, gg);

    // ffn_out + residual -> out
    {
        dim3 g(M_TOT / 128, 1);
        gemm_kernel<2><<<g, 256>>>(gg, fow, out, x2, M_TOT, 64, 128, 0);
    }
}

// round 3
// speedup vs baseline: 1.6943x; 1.6943x over previous
#include <cuda_runtime.h>
#include <cuda_bf16.h>
#include <mma.h>

using namespace nvcuda;

// ---------------------------------------------------------------------------
// Problem constants
// ---------------------------------------------------------------------------
#define NB      4
#define CDIM    64
#define HW      65536          // 256*256
#define NWIN    1024           // 4 * 16 * 16
#define DIN     128            // d_inner
#define NDBL    36             // dt_rank + 2*d_state
#define M_TOT   (NWIN * 256)   // 262144 token positions

// ---------------------------------------------------------------------------
// Scratch (static device globals — allocation-free per harness rules)
// ---------------------------------------------------------------------------
__device__ __align__(16) __nv_bfloat16 g_xw [M_TOT * CDIM];  // LN2 out, windowed
__device__ __align__(16) __nv_bfloat16 g_xz [M_TOT * 256];   // in_proj out (xm|z)
__device__ __align__(16) __nv_bfloat16 g_xc [M_TOT * DIN];   // conv+silu out
__device__ __align__(16) float         g_dbl[M_TOT * NDBL];  // x_proj out (dt|B|C)
__device__ __align__(16) __nv_bfloat16 g_y  [M_TOT * DIN];   // scan+gate out
__device__ __align__(16) float         g_x2 [NB * CDIM * HW];// x + attn (NCHW)
__device__ __align__(16) __nv_bfloat16 g_y2 [M_TOT * CDIM];  // LN3 out, pos-major
__device__ __align__(16) __nv_bfloat16 g_hid[M_TOT * 256];   // ffn_in out
__device__ __align__(16) __nv_bfloat16 g_g  [M_TOT * DIN];   // gelu(h1)*h2
__device__ float g_Atab[DIN * 16];
__device__ int   g_flag;

// ---------------------------------------------------------------------------
// prep: A table + structure flag (A[d][s] == -(s+1) fast path)
// ---------------------------------------------------------------------------
__global__ void prep_kernel(const float* __restrict__ alog,
                            float* __restrict__ Atab, int* __restrict__ flag)
{
    __shared__ int ok_s;
    if (threadIdx.x == 0) ok_s = 1;
    __syncthreads();
    bool ok = true;
    for (int i = threadIdx.x; i < DIN * 16; i += 256) {
        float a = -expf(alog[i]);
        Atab[i] = a;
        int s = i & 15;
        if (fabsf(a + (float)(s + 1)) > 1e-3f * (float)(s + 1)) ok = false;
    }
    if (!ok) atomicAnd(&ok_s, 0);
    __syncthreads();
    if (threadIdx.x == 0) *flag = ok_s;
}

// ---------------------------------------------------------------------------
// Channel LayerNorm -> bf16.
// mode 0: windowed layout (win*256+l, c).  mode 1: pos-major (b*65536+hw, c).
// ---------------------------------------------------------------------------
__global__ void __launch_bounds__(256) ln_kernel(
    const float* __restrict__ x, const float* __restrict__ gam,
    const float* __restrict__ bet, __nv_bfloat16* __restrict__ out, int mode)
{
    __shared__ float s[64][65];
    __shared__ float mu[64], rs[64];
    int tid  = threadIdx.x;
    int blk  = blockIdx.x;
    int bimg = blk >> 10;
    int rem  = blk & 1023;
    int h    = rem >> 2;
    int w0   = (rem & 3) << 6;
    const float* xb = x + ((bimg * CDIM) << 16) + (h << 8) + w0;

#pragma unroll
    for (int i = 0; i < 16; i++) {
        int idx = i * 256 + tid;
        int c = idx >> 6, p = idx & 63;
        s[p][c] = xb[(c << 16) + p];
    }
    __syncthreads();
    if (tid < 64) {
        float sum = 0.f, sq = 0.f;
#pragma unroll
        for (int c = 0; c < 64; c++) { float v = s[tid][c]; sum += v; sq += v * v; }
        float m = sum * (1.f / 64.f);
        float var = sq * (1.f / 64.f) - m * m;
        mu[tid] = m;
        rs[tid] = rsqrtf(var + 1e-5f);
    }
    __syncthreads();
#pragma unroll
    for (int i = 0; i < 16; i++) {
        int c = tid & 63;
        int p = (i << 2) + (tid >> 6);
        float v = (s[p][c] - mu[p]) * rs[p] * gam[c] + bet[c];
        int wg = w0 + p;
        int addr;
        if (mode == 0) {
            int win = (bimg << 8) + ((h >> 4) << 4) + (wg >> 4);
            int l   = ((h & 15) << 4) + (wg & 15);
            addr = ((win << 8) + l) * CDIM + c;
        } else {
            addr = (((bimg << 16) + (h << 8) + wg) << 6) + c;
        }
        out[addr] = __float2bfloat16(v);
    }
}

// ---------------------------------------------------------------------------
// Tensor-core GEMM: C[M,N] = A[M,K](bf16) @ W[N,K]^T(fp32->bf16)
// Block tile 128x64, 256 threads (8 warps, 4x2), warp tile 32x32, BK=64.
// EP 0: plain store (OUTBF: bf16 else fp32, guarded n<N)
// EP 1: out_proj: windowed m -> NCHW scatter, C = res + acc (fp32)
// EP 2: ffn_out:  pos-major m -> NCHW scatter, C = res + acc (fp32)
// ---------------------------------------------------------------------------
template<int EP, bool OUTBF>
__global__ void __launch_bounds__(256) gemm_tc(
    const __nv_bfloat16* __restrict__ A, const float* __restrict__ W,
    void* __restrict__ Cout, const float* __restrict__ res,
    int M, int N, int K, int ldc)
{
    __shared__ __align__(16) unsigned char smem_raw[34816];
    __nv_bfloat16* As = (__nv_bfloat16*)smem_raw;   // [128][72]
    __nv_bfloat16* Ws = As + 128 * 72;              // [64][72]
    float* epi = (float*)smem_raw;                  // [128][68]
    static_assert(128 * 72 * 2 + 64 * 72 * 2 <= 34816, "operand smem");
    static_assert(128 * 68 * 4 <= 34816, "epilogue smem");

    int tid = threadIdx.x;
    int wid = tid >> 5;
    int wm = wid >> 1, wn = wid & 1;
    int m0 = blockIdx.x * 128;
    int n0 = blockIdx.y * 64;

    wmma::fragment<wmma::accumulator, 16, 16, 16, float> c[2][2];
#pragma unroll
    for (int i = 0; i < 2; i++)
#pragma unroll
        for (int j = 0; j < 2; j++) wmma::fill_fragment(c[i][j], 0.f);

    for (int k0 = 0; k0 < K; k0 += 64) {
        // A tile: 128x64 bf16, vectorized 16B copies
#pragma unroll
        for (int i = 0; i < 4; i++) {
            int idx = tid + i * 256;
            int r = idx >> 3, v = idx & 7;
            *(uint4*)&As[r * 72 + v * 8] =
                *(const uint4*)&A[(m0 + r) * K + k0 + v * 8];
        }
        // W tile: 64x64, fp32 -> bf16 convert, zero-pad rows >= N
#pragma unroll
        for (int i = 0; i < 4; i++) {
            int idx = tid + i * 256;
            int r = idx >> 4, v = idx & 15;
            float4 f = make_float4(0.f, 0.f, 0.f, 0.f);
            if (n0 + r < N) f = *(const float4*)&W[(n0 + r) * K + k0 + v * 4];
            __nv_bfloat16* dst = &Ws[r * 72 + v * 4];
            dst[0] = __float2bfloat16(f.x);
            dst[1] = __float2bfloat16(f.y);
            dst[2] = __float2bfloat16(f.z);
            dst[3] = __float2bfloat16(f.w);
        }
        __syncthreads();
#pragma unroll
        for (int kk = 0; kk < 64; kk += 16) {
            wmma::fragment<wmma::matrix_a, 16, 16, 16, __nv_bfloat16, wmma::row_major> a[2];
            wmma::fragment<wmma::matrix_b, 16, 16, 16, __nv_bfloat16, wmma::col_major> b[2];
#pragma unroll
            for (int i = 0; i < 2; i++)
                wmma::load_matrix_sync(a[i], &As[(wm * 32 + i * 16) * 72 + kk], 72);
#pragma unroll
            for (int j = 0; j < 2; j++)
                wmma::load_matrix_sync(b[j], &Ws[(wn * 32 + j * 16) * 72 + kk], 72);
#pragma unroll
            for (int i = 0; i < 2; i++)
#pragma unroll
                for (int j = 0; j < 2; j++)
                    wmma::mma_sync(c[i][j], a[i], b[j], c[i][j]);
        }
        __syncthreads();
    }

    // dump accumulators to shared (aliases As/Ws — safe after sync above)
#pragma unroll
    for (int i = 0; i < 2; i++)
#pragma unroll
        for (int j = 0; j < 2; j++)
            wmma::store_matrix_sync(&epi[(wm * 32 + i * 16) * 68 + wn * 32 + j * 16],
                                    c[i][j], 68, wmma::mem_row_major);
    __syncthreads();

    if (EP == 0) {
        if (OUTBF) {
            __nv_bfloat16* Cb = (__nv_bfloat16*)Cout;
#pragma unroll
            for (int i = 0; i < 16; i++) {
                int idx = tid + i * 256;          // 0..4095 (pairs)
                int r = idx >> 5, cp = (idx & 31) * 2;
                __nv_bfloat162 pk = __floats2bfloat162_rn(epi[r * 68 + cp],
                                                          epi[r * 68 + cp + 1]);
                *(__nv_bfloat162*)&Cb[(m0 + r) * ldc + n0 + cp] = pk;
            }
        } else {
            float* Cf = (float*)Cout;
#pragma unroll
            for (int i = 0; i < 32; i++) {
                int idx = tid + i * 256;          // 0..8191
                int r = idx >> 6, cn = idx & 63;
                int n = n0 + cn;
                if (n < N) Cf[(m0 + r) * ldc + n] = epi[r * 68 + cn];
            }
        }
    } else {
        float* Cf = (float*)Cout;
#pragma unroll
        for (int i = 0; i < 32; i++) {
            int idx = tid + i * 256;
            int n = idx >> 7;                     // channel
            int r = idx & 127;                    // row (coalesced over m)
            float v = epi[r * 68 + n];
            int m = m0 + r;
            int addr;
            if (EP == 1) {
                int win = m >> 8, l = m & 255;
                int b = win >> 8, widx = win & 255;
                int h = ((widx >> 4) << 4) + (l >> 4);
                int w = ((widx & 15) << 4) + (l & 15);
                addr = ((b * CDIM + n) << 16) + (h << 8) + w;
            } else {
                int b = m >> 16, hw = m & 65535;
                addr = ((b * CDIM + n) << 16) + hw;
            }
            Cf[addr] = res[addr] + v;
        }
    }
}

// ---------------------------------------------------------------------------
// Depthwise causal conv1d (k=4, left pad 3) + bias + SiLU.  bf16 in/out.
// ---------------------------------------------------------------------------
__global__ void __launch_bounds__(256) conv_kernel(
    const __nv_bfloat16* __restrict__ xz, const float* __restrict__ cw,
    const float* __restrict__ cb, __nv_bfloat16* __restrict__ xc)
{
    int gid = blockIdx.x * 256 + threadIdx.x;
    int d = gid & 127;
    int m = gid >> 7;
    int t = m & 255;
    float acc = cb[d];
    const __nv_bfloat16* base = xz + ((long)(m - 3) << 8) + d;
#pragma unroll
    for (int j = 0; j < 4; j++) {
        int tt = t - 3 + j;
        if (tt >= 0)
            acc += cw[(d << 2) + j] * __bfloat162float(base[j << 8]);
    }
    float e = __expf(-acc);
    xc[gid] = __float2bfloat16(__fdividef(acc, 1.f + e));
}

// ---------------------------------------------------------------------------
// Selective scan + fused dt_proj/softplus + D skip + SiLU(z) gate.
// One block per window, thread = channel d, 16 states in registers.
// ---------------------------------------------------------------------------
__global__ void __launch_bounds__(128) scan_kernel(
    const float* __restrict__ dbl, const __nv_bfloat16* __restrict__ xc,
    const __nv_bfloat16* __restrict__ xz, const float* __restrict__ dtw,
    const float* __restrict__ dtb, const float* __restrict__ Dv,
    const float* __restrict__ Atab, const int* __restrict__ flagp,
    __nv_bfloat16* __restrict__ yout)
{
    int win = blockIdx.x;
    int d = threadIdx.x;
    int fl = *flagp;
    float Dd = Dv[d];
    float4 wv = *(const float4*)&dtw[d << 2];
    float bb = dtb[d];
    float h[16];
#pragma unroll
    for (int s = 0; s < 16; s++) h[s] = 0.f;
    int mbase = win << 8;

    for (int t = 0; t < 256; t++) {
        int m = mbase + t;
        const float* row = dbl + m * NDBL;
        float4 q = *(const float4*)row;
        float pre = bb + q.x * wv.x + q.y * wv.y + q.z * wv.z + q.w * wv.w;
        float dtv = (pre > 15.f) ? pre : log1pf(__expf(pre));
        float u  = __bfloat162float(xc[(m << 7) + d]);
        float zv = __bfloat162float(xz[(m << 8) + 128 + d]);
        float4 B0 = *(const float4*)(row + 4);
        float4 B1 = *(const float4*)(row + 8);
        float4 B2 = *(const float4*)(row + 12);
        float4 B3 = *(const float4*)(row + 16);
        float4 C0 = *(const float4*)(row + 20);
        float4 C1 = *(const float4*)(row + 24);
        float4 C2 = *(const float4*)(row + 28);
        float4 C3 = *(const float4*)(row + 32);
        float Bv[16] = {B0.x,B0.y,B0.z,B0.w, B1.x,B1.y,B1.z,B1.w,
                        B2.x,B2.y,B2.z,B2.w, B3.x,B3.y,B3.z,B3.w};
        float Cv[16] = {C0.x,C0.y,C0.z,C0.w, C1.x,C1.y,C1.z,C1.w,
                        C2.x,C2.y,C2.z,C2.w, C3.x,C3.y,C3.z,C3.w};
        float dtu = dtv * u;
        float yv = 0.f;
        if (fl) {
            float r = __expf(-dtv);
            float p = r;
#pragma unroll
            for (int s = 0; s < 16; s++) {
                h[s] = h[s] * p + dtu * Bv[s];
                yv += h[s] * Cv[s];
                p *= r;
            }
        } else {
#pragma unroll
            for (int s = 0; s < 16; s++) {
                float dec = __expf(dtv * Atab[(d << 4) + s]);
                h[s] = h[s] * dec + dtu * Bv[s];
                yv += h[s] * Cv[s];
            }
        }
        yv += u * Dd;
        float sg = __fdividef(1.f, 1.f + __expf(-zv));
        yout[(m << 7) + d] = __float2bfloat16(yv * zv * sg);
    }
}

// ---------------------------------------------------------------------------
// Depthwise 3x3 SAME conv + exact-GELU gate.  bf16 in/out.
// ---------------------------------------------------------------------------
__global__ void __launch_bounds__(256) dw_kernel(
    const __nv_bfloat16* __restrict__ hid, const float* __restrict__ dww,
    __nv_bfloat16* __restrict__ gout)
{
    int gid = blockIdx.x * 256 + threadIdx.x;
    int c = gid & 127;
    int m = gid >> 7;
    int b = m >> 16, hw = m & 65535;
    int h = hw >> 8, w = hw & 255;
    float a1 = 0.f, a2 = 0.f;
#pragma unroll
    for (int dy = 0; dy < 3; dy++) {
        int hh = h + dy - 1;
        if (hh < 0 || hh > 255) continue;
#pragma unroll
        for (int dx = 0; dx < 3; dx++) {
            int ww = w + dx - 1;
            if (ww < 0 || ww > 255) continue;
            int mm = (b << 16) + (hh << 8) + ww;
            const __nv_bfloat16* row = hid + (mm << 8);
            a1 += dww[c * 9 + dy * 3 + dx] * __bfloat162float(row[c]);
            a2 += dww[(c + 128) * 9 + dy * 3 + dx] * __bfloat162float(row[c + 128]);
        }
    }
    float gl = 0.5f * a1 * (1.f + erff(a1 * 0.70710678118f));
    gout[gid] = __float2bfloat16(gl * a2);
}

// ---------------------------------------------------------------------------
// launch
// ---------------------------------------------------------------------------
extern "C" void kernel_launch(void* const* d_in, const int* in_sizes, int n_in,
                              void* d_out, int out_size)
{
    (void)in_sizes; (void)n_in; (void)out_size;
    const float* x     = (const float*)d_in[0];
    const float* ln2w  = (const float*)d_in[1];
    const float* ln2b  = (const float*)d_in[2];
    const float* ln3w  = (const float*)d_in[3];
    const float* ln3b  = (const float*)d_in[4];
    const float* inpw  = (const float*)d_in[5];
    const float* convw = (const float*)d_in[6];
    const float* convb = (const float*)d_in[7];
    const float* xpw   = (const float*)d_in[8];
    const float* dtw   = (const float*)d_in[9];
    const float* dtb   = (const float*)d_in[10];
    const float* alog  = (const float*)d_in[11];
    const float* Dv    = (const float*)d_in[12];
    const float* outw  = (const float*)d_in[13];
    const float* fiw   = (const float*)d_in[14];
    const float* fdw   = (const float*)d_in[15];
    const float* fow   = (const float*)d_in[16];
    float* out = (float*)d_out;

    __nv_bfloat16 *xw, *xz, *xc, *yb, *y2, *hid, *gg;
    float *dbl, *x2, *Atab;
    int* flag;
    cudaGetSymbolAddress((void**)&xw,  g_xw);
    cudaGetSymbolAddress((void**)&xz,  g_xz);
    cudaGetSymbolAddress((void**)&xc,  g_xc);
    cudaGetSymbolAddress((void**)&dbl, g_dbl);
    cudaGetSymbolAddress((void**)&yb,  g_y);
    cudaGetSymbolAddress((void**)&x2,  g_x2);
    cudaGetSymbolAddress((void**)&y2,  g_y2);
    cudaGetSymbolAddress((void**)&hid, g_hid);
    cudaGetSymbolAddress((void**)&gg,  g_g);
    cudaGetSymbolAddress((void**)&Atab, g_Atab);
    cudaGetSymbolAddress((void**)&flag, g_flag);

    prep_kernel<<<1, 256>>>(alog, Atab, flag);

    // LN2 + window partition -> bf16
    ln_kernel<<<4096, 256>>>(x, ln2w, ln2b, xw, 0);

    // in_proj: (262144,64) @ (256,64)^T -> xz (bf16)
    {
        dim3 g(M_TOT / 128, 4);
        gemm_tc<0, true><<<g, 256>>>(xw, inpw, xz, nullptr, M_TOT, 256, 64, 256);
    }

    // depthwise causal conv1d + silu
    conv_kernel<<<(M_TOT * DIN) / 256, 256>>>(xz, convw, convb, xc);

    // x_proj: (262144,128) @ (36,128)^T -> dbl (fp32)
    {
        dim3 g(M_TOT / 128, 1);
        gemm_tc<0, false><<<g, 256>>>(xc, xpw, dbl, nullptr, M_TOT, NDBL, 128, NDBL);
    }

    // selective scan (fused dt_proj+softplus) + D skip + silu(z) gate
    scan_kernel<<<NWIN, 128>>>(dbl, xc, xz, dtw, dtb, Dv, Atab, flag, yb);

    // out_proj + un-window + residual -> x2 (fp32)
    {
        dim3 g(M_TOT / 128, 1);
        gemm_tc<1, false><<<g, 256>>>(yb, outw, x2, x, M_TOT, 64, 128, 0);
    }

    // LN3 -> y2 (pos-major, bf16)
    ln_kernel<<<4096, 256>>>(x2, ln3w, ln3b, y2, 1);

    // ffn_in: (262144,64) @ (256,64)^T -> hid (bf16)
    {
        dim3 g(M_TOT / 128, 4);
        gemm_tc<0, true><<<g, 256>>>(y2, fiw, hid, nullptr, M_TOT, 256, 64, 256);
    }

    // depthwise 3x3 + gelu gate -> gg
    dw_kernel<<<(M_TOT * DIN) / 256, 256>>>(hid, fdw, gg);

    // ffn_out + residual -> out
    {
        dim3 g(M_TOT / 128, 1);
        gemm_tc<2, false><<<g, 256>>>(gg, fow, out, x2, M_TOT, 64, 128, 0);
    }
}